// round 10
// baseline (speedup 1.0000x reference)
#include <cuda_runtime.h>
#include <cstdint>

// Fixed problem shapes
#define IMG_H 544
#define IMG_W 960
#define OUT_H 136
#define OUT_W 240

// Each WARP produces a 30x4 output strip (120x16 mag region) streaming 22
// input rows. Raw RGB rows are prefetched global->shared via cp.async into a
// per-warp 4-slot ring (distance-4), consumed via LDS; all filter state in regs.
#define TW 30
#define NROWS 22
#define D 4                 // ring depth (rows)

// Normalized 1D Gaussian, k=5, sigma=1.5
#define GW0 0.120078385f
#define GW1 0.233880757f
#define GW2 0.292081718f

__device__ __forceinline__ int reflect_idx(int i, int n) {
    if (i < 0) i = -i;
    if (i >= n) i = 2 * n - 2 - i;
    return i;
}

__device__ __forceinline__ float sqrt_approx(float x) {
    float r;
    asm("sqrt.approx.f32 %0, %1;" : "=f"(r) : "f"(x));
    return r;
}

__device__ __forceinline__ void cp16(uint32_t dst, const float* src) {
    asm volatile("cp.async.cg.shared.global [%0], [%1], 16;" :: "r"(dst), "l"(src));
}
__device__ __forceinline__ void cp4(uint32_t dst, const float* src) {
    asm volatile("cp.async.ca.shared.global [%0], [%1], 4;" :: "r"(dst), "l"(src));
}
__device__ __forceinline__ void cpcommit() {
    asm volatile("cp.async.commit_group;" ::: "memory");
}
template <int N>
__device__ __forceinline__ void cpwait() {
    asm volatile("cp.async.wait_group %0;" :: "n"(N) : "memory");
}

__global__ __launch_bounds__(128, 8)
void EdgeGuidance_47313359733145_kernel(const float* __restrict__ in,
                                        float* __restrict__ out)
{
    // Per-warp ring: D rows x 3 planes x 128 floats (512B per plane-row)
    __shared__ float ring[4][D][3][128];

    const int lane = threadIdx.x & 31;
    const int wid  = threadIdx.x >> 5;
    const int ct   = blockIdx.x * 4 + wid;   // column tile 0..7 (30 out cols)
    const int by   = blockIdx.y;             // row strip 0..33  (4 out rows)
    const int b    = blockIdx.z;             // batch

    const int mx0 = ct * (TW * 4);
    const int my0 = by * 16;

    const float* __restrict__ pr = in + (size_t)b * 3 * IMG_H * IMG_W;
    const float* __restrict__ pg = pr + IMG_H * IMG_W;
    const float* __restrict__ pb = pg + IMG_H * IMG_W;

    const int gx0 = mx0 - 4 + (lane << 2);
    const bool xfast = (gx0 >= 0) && (gx0 + 3 < IMG_W);

    const int gsx = mx0 - 1 + (lane << 2);
    const bool vx0 = (gsx + 0 >= 0) && (gsx + 0 < IMG_W);
    const bool vx1 = (gsx + 1 >= 0) && (gsx + 1 < IMG_W);
    const bool vx2 = (gsx + 2 < IMG_W);
    const bool vx3 = (gsx + 3 < IMG_W);

    const unsigned FULL = 0xffffffffu;

    const uint32_t rbase =
        (uint32_t)__cvta_generic_to_shared(&ring[wid][0][0][0]) + lane * 16;
    // slot s, plane p: rbase + s*1536 + p*512

    // Issue cp.async for input row t (global row reflect(my0-3+t)) into slot t%D.
    auto issue_row = [&](int t) {
        const int s = t & (D - 1);
        const int gy = reflect_idx(my0 - 3 + t, IMG_H);
        const size_t rowoff = (size_t)gy * IMG_W;
        const uint32_t dst = rbase + s * 1536;
        if (xfast) {
            cp16(dst,        pr + rowoff + gx0);
            cp16(dst +  512, pg + rowoff + gx0);
            cp16(dst + 1024, pb + rowoff + gx0);
        } else {
            #pragma unroll
            for (int e = 0; e < 4; e++) {
                const int gx = reflect_idx(gx0 + e, IMG_W);
                cp4(dst + e * 4,        pr + rowoff + gx);
                cp4(dst +  512 + e * 4, pg + rowoff + gx);
                cp4(dst + 1024 + e * 4, pb + rowoff + gx);
            }
        }
        cpcommit();
    };

    // Consume row t from its ring slot: gray conversion + horizontal blur.
    auto consume_row = [&](int t) -> float4 {
        const int s = t & (D - 1);
        const float4 r4 = *reinterpret_cast<const float4*>(&ring[wid][s][0][lane << 2]);
        const float4 g4 = *reinterpret_cast<const float4*>(&ring[wid][s][1][lane << 2]);
        const float4 b4 = *reinterpret_cast<const float4*>(&ring[wid][s][2][lane << 2]);
        float4 A;
        A.x = fmaf(0.2989f, r4.x, fmaf(0.587f, g4.x, 0.114f * b4.x));
        A.y = fmaf(0.2989f, r4.y, fmaf(0.587f, g4.y, 0.114f * b4.y));
        A.z = fmaf(0.2989f, r4.z, fmaf(0.587f, g4.z, 0.114f * b4.z));
        A.w = fmaf(0.2989f, r4.w, fmaf(0.587f, g4.w, 0.114f * b4.w));

        const float Bx = __shfl_down_sync(FULL, A.x, 1);
        const float By = __shfl_down_sync(FULL, A.y, 1);
        const float Bz = __shfl_down_sync(FULL, A.z, 1);
        const float Bw = __shfl_down_sync(FULL, A.w, 1);
        const float C0 = __shfl_down_sync(FULL, A.x, 2);

        float4 o4;
        o4.x = fmaf(GW0, A.y, fmaf(GW1, A.z, fmaf(GW2, A.w, fmaf(GW1, Bx, GW0 * By))));
        o4.y = fmaf(GW0, A.z, fmaf(GW1, A.w, fmaf(GW2, Bx, fmaf(GW1, By, GW0 * Bz))));
        o4.z = fmaf(GW0, A.w, fmaf(GW1, Bx, fmaf(GW2, By, fmaf(GW1, Bz, GW0 * Bw))));
        o4.w = fmaf(GW0, Bx, fmaf(GW1, By, fmaf(GW2, Bz, fmaf(GW1, Bw, GW0 * C0))));
        return o4;
    };

    // Prologue: fill ring with rows 0..3; consume 0..3 while issuing 4..7.
    issue_row(0); issue_row(1); issue_row(2); issue_row(3);
    cpwait<3>(); float4 hb0 = consume_row(0); issue_row(4);
    cpwait<3>(); float4 hb1 = consume_row(1); issue_row(5);
    cpwait<3>(); float4 hb2 = consume_row(2); issue_row(6);
    cpwait<3>(); float4 hb3 = consume_row(3); issue_row(7);
    // Invariant at iter r: rows r+4..r+7 committed (last group = row min(r+7,21)).

    float w0[6], w1[6], w2[6];
    float acc = 0.0f;

    const size_t outbase = ((size_t)b * OUT_H + by * 4) * OUT_W + ct * TW + lane;

    #pragma unroll
    for (int r = 0; r < 18; ++r) {
        // Wait for row r+4 (groups after it: min(3, 17-r); r is a literal here)
        if (r <= 14)      cpwait<3>();
        else if (r == 15) cpwait<2>();
        else if (r == 16) cpwait<1>();
        else              cpwait<0>();

        const float4 h4 = consume_row(r + 4);
        if (r + 8 <= NROWS - 1) issue_row(r + 8);   // refill freed slot (distance 4)

        // Vertical Gaussian -> gs row r (global gy = my0-1+r)
        float4 g;
        g.x = fmaf(GW0, hb0.x, fmaf(GW1, hb1.x, fmaf(GW2, hb2.x, fmaf(GW1, hb3.x, GW0 * h4.x))));
        g.y = fmaf(GW0, hb0.y, fmaf(GW1, hb1.y, fmaf(GW2, hb2.y, fmaf(GW1, hb3.y, GW0 * h4.y))));
        g.z = fmaf(GW0, hb0.z, fmaf(GW1, hb1.z, fmaf(GW2, hb2.z, fmaf(GW1, hb3.z, GW0 * h4.z))));
        g.w = fmaf(GW0, hb0.w, fmaf(GW1, hb1.w, fmaf(GW2, hb2.w, fmaf(GW1, hb3.w, GW0 * h4.w))));

        const int gy = my0 - 1 + r;
        const bool yok = (gy >= 0) && (gy < IMG_H);
        g.x = (yok && vx0) ? g.x : 0.0f;
        g.y = (yok && vx1) ? g.y : 0.0f;
        g.z = (yok && vx2) ? g.z : 0.0f;
        g.w = (yok && vx3) ? g.w : 0.0f;

        w2[0] = g.x; w2[1] = g.y; w2[2] = g.z; w2[3] = g.w;
        w2[4] = __shfl_down_sync(FULL, g.x, 1);
        w2[5] = __shfl_down_sync(FULL, g.y, 1);

        if (r >= 2) {
            // Sobel + magnitude for mag row m = r-2 (uses gs rows r-2, r-1, r)
            float cv[6];
            #pragma unroll
            for (int c = 0; c < 6; c++) cv[c] = w0[c] + 2.0f * w1[c] + w2[c];

            #pragma unroll
            for (int c = 1; c <= 4; c++) {
                const float sgx = cv[c + 1] - cv[c - 1];
                const float sgy = (w2[c - 1] + 2.0f * w2[c] + w2[c + 1])
                                - (w0[c - 1] + 2.0f * w0[c] + w0[c + 1]);
                acc += sqrt_approx(fmaf(sgx, sgx, fmaf(sgy, sgy, 1e-6f)));
            }

            if (((r - 2) & 3) == 3) {        // r = 5, 9, 13, 17 -> 4 output rows
                const float down = acc * (1.0f / 16.0f);
                const float e = __expf(-5.0f * (down - 0.2f));
                const float sg = __fdividef(1.0f, 1.0f + e);
                if (lane < TW) {
                    out[outbase + (size_t)((r - 5) >> 2) * OUT_W] = sg * sg;
                }
                acc = 0.0f;
            }
        }

        // Shift windows (register renames under full unroll)
        hb0 = hb1; hb1 = hb2; hb2 = hb3; hb3 = h4;
        #pragma unroll
        for (int c = 0; c < 6; c++) { w0[c] = w1[c]; w1[c] = w2[c]; }
    }
}

extern "C" void kernel_launch(void* const* d_in, const int* in_sizes, int n_in,
                              void* d_out, int out_size)
{
    const float* in = (const float*)d_in[0];
    float* out = (float*)d_out;

    // 8 col tiles (4 warps per block) x 34 row strips x 16 batch
    dim3 grid(2, 34, 16);                    // 1088 blocks of 128 threads
    EdgeGuidance_47313359733145_kernel<<<grid, 128>>>(in, out);
}

// round 11
// speedup vs baseline: 1.2852x; 1.2852x over previous
#include <cuda_runtime.h>
#include <cuda_bf16.h>

// Fixed problem shapes
#define IMG_H 544
#define IMG_W 960
#define OUT_H 136
#define OUT_W 240

// Each WARP produces a 30x8 output strip (120x32 mag region) by streaming
// 38 input rows with all intermediates in registers (no shared memory).
// 4-slot raw RGB ring buffer: load row r+7 at top of iter r (slot (r+7)&3),
// consume row r+4 (slot (r+4)&3) -- distinct slots, so the LDG issues first.
// 64-thread blocks + launch_bounds(64,7) -> 146-reg budget.
#define TW 30

// Normalized 1D Gaussian, k=5, sigma=1.5
#define GW0 0.120078385f
#define GW1 0.233880757f
#define GW2 0.292081718f

__device__ __forceinline__ int reflect_idx(int i, int n) {
    if (i < 0) i = -i;
    if (i >= n) i = 2 * n - 2 - i;
    return i;
}

__device__ __forceinline__ float sqrt_approx(float x) {
    float r;
    asm("sqrt.approx.f32 %0, %1;" : "=f"(r) : "f"(x));
    return r;
}

__global__ __launch_bounds__(64, 7)
void EdgeGuidance_47313359733145_kernel(const float* __restrict__ in,
                                        float* __restrict__ out)
{
    const int lane = threadIdx.x & 31;
    const int wid  = threadIdx.x >> 5;
    const int ct   = blockIdx.x * 2 + wid;   // column tile 0..7 (30 out cols)
    const int by   = blockIdx.y;             // row strip 0..16  (8 out rows)
    const int b    = blockIdx.z;             // batch

    const int mx0 = ct * (TW * 4);
    const int my0 = by * 32;

    const float* __restrict__ pr = in + (size_t)b * 3 * IMG_H * IMG_W;
    const float* __restrict__ pg = pr + IMG_H * IMG_W;
    const float* __restrict__ pb = pg + IMG_H * IMG_W;

    const int gx0 = mx0 - 4 + (lane << 2);
    const bool xfast = (gx0 >= 0) && (gx0 + 3 < IMG_W);
    const int rx0 = reflect_idx(gx0 + 0, IMG_W);
    const int rx1 = reflect_idx(gx0 + 1, IMG_W);
    const int rx2 = reflect_idx(gx0 + 2, IMG_W);
    const int rx3 = reflect_idx(gx0 + 3, IMG_W);

    const int gsx = mx0 - 1 + (lane << 2);
    const bool vx0 = (gsx + 0 >= 0) && (gsx + 0 < IMG_W);
    const bool vx1 = (gsx + 1 >= 0) && (gsx + 1 < IMG_W);
    const bool vx2 = (gsx + 2 < IMG_W);
    const bool vx3 = (gsx + 3 < IMG_W);

    const unsigned FULL = 0xffffffffu;

    // 4-slot raw RGB ring buffer
    float4 RB[4], GB[4], BB[4];

    auto loadraw = [&](int t) {
        const int s = t & 3;                 // compile-time under full unroll
        const int gy = reflect_idx(my0 - 3 + t, IMG_H);
        const int rowoff = gy * IMG_W;
        if (xfast) {
            RB[s] = *reinterpret_cast<const float4*>(pr + rowoff + gx0);
            GB[s] = *reinterpret_cast<const float4*>(pg + rowoff + gx0);
            BB[s] = *reinterpret_cast<const float4*>(pb + rowoff + gx0);
        } else {
            RB[s] = make_float4(pr[rowoff + rx0], pr[rowoff + rx1], pr[rowoff + rx2], pr[rowoff + rx3]);
            GB[s] = make_float4(pg[rowoff + rx0], pg[rowoff + rx1], pg[rowoff + rx2], pg[rowoff + rx3]);
            BB[s] = make_float4(pb[rowoff + rx0], pb[rowoff + rx1], pb[rowoff + rx2], pb[rowoff + rx3]);
        }
    };

    // gray conversion + horizontal blur (shuffle-based) of raw row t
    auto gb = [&](int t) -> float4 {
        const int s = t & 3;
        const float4 r4 = RB[s], g4 = GB[s], b4 = BB[s];
        float4 A;
        A.x = fmaf(0.2989f, r4.x, fmaf(0.587f, g4.x, 0.114f * b4.x));
        A.y = fmaf(0.2989f, r4.y, fmaf(0.587f, g4.y, 0.114f * b4.y));
        A.z = fmaf(0.2989f, r4.z, fmaf(0.587f, g4.z, 0.114f * b4.z));
        A.w = fmaf(0.2989f, r4.w, fmaf(0.587f, g4.w, 0.114f * b4.w));

        const float Bx = __shfl_down_sync(FULL, A.x, 1);
        const float By = __shfl_down_sync(FULL, A.y, 1);
        const float Bz = __shfl_down_sync(FULL, A.z, 1);
        const float Bw = __shfl_down_sync(FULL, A.w, 1);
        const float C0 = __shfl_down_sync(FULL, A.x, 2);

        float4 o4;
        o4.x = fmaf(GW0, A.y, fmaf(GW1, A.z, fmaf(GW2, A.w, fmaf(GW1, Bx, GW0 * By))));
        o4.y = fmaf(GW0, A.z, fmaf(GW1, A.w, fmaf(GW2, Bx, fmaf(GW1, By, GW0 * Bz))));
        o4.z = fmaf(GW0, A.w, fmaf(GW1, Bx, fmaf(GW2, By, fmaf(GW1, Bz, GW0 * Bw))));
        o4.w = fmaf(GW0, Bx, fmaf(GW1, By, fmaf(GW2, Bz, fmaf(GW1, Bw, GW0 * C0))));
        return o4;
    };

    // Prologue: fill ring rows 0..3, build hb window rows 0..3, load 4..6.
    loadraw(0); loadraw(1); loadraw(2); loadraw(3);
    float4 hb0 = gb(0); loadraw(4);
    float4 hb1 = gb(1); loadraw(5);
    float4 hb2 = gb(2); loadraw(6);
    float4 hb3 = gb(3);
    // Invariant entering iter r: ring holds raw rows r+4, r+5, r+6 (+ stale r+3).

    float w0[6], w1[6], w2[6];
    float acc = 0.0f;

    const size_t outbase = ((size_t)b * OUT_H + by * 8) * OUT_W + ct * TW + lane;

    #pragma unroll
    for (int r = 0; r < 34; ++r) {
        // Issue next load FIRST (slot (r+7)&3 is free: holds stale row r+3)
        if (r + 7 <= 37) loadraw(r + 7);

        const float4 h4 = gb(r + 4);         // consume raw(r+4), loaded at iter r-3

        // Vertical Gaussian -> gs row r (global gy = my0-1+r)
        float4 g;
        g.x = fmaf(GW0, hb0.x, fmaf(GW1, hb1.x, fmaf(GW2, hb2.x, fmaf(GW1, hb3.x, GW0 * h4.x))));
        g.y = fmaf(GW0, hb0.y, fmaf(GW1, hb1.y, fmaf(GW2, hb2.y, fmaf(GW1, hb3.y, GW0 * h4.y))));
        g.z = fmaf(GW0, hb0.z, fmaf(GW1, hb1.z, fmaf(GW2, hb2.z, fmaf(GW1, hb3.z, GW0 * h4.z))));
        g.w = fmaf(GW0, hb0.w, fmaf(GW1, hb1.w, fmaf(GW2, hb2.w, fmaf(GW1, hb3.w, GW0 * h4.w))));

        const int gy = my0 - 1 + r;
        const bool yok = (gy >= 0) && (gy < IMG_H);
        g.x = (yok && vx0) ? g.x : 0.0f;
        g.y = (yok && vx1) ? g.y : 0.0f;
        g.z = (yok && vx2) ? g.z : 0.0f;
        g.w = (yok && vx3) ? g.w : 0.0f;

        w2[0] = g.x; w2[1] = g.y; w2[2] = g.z; w2[3] = g.w;
        w2[4] = __shfl_down_sync(FULL, g.x, 1);
        w2[5] = __shfl_down_sync(FULL, g.y, 1);

        if (r >= 2) {
            // Sobel + magnitude for mag row m = r-2 (uses gs rows r-2, r-1, r)
            float cv[6];
            #pragma unroll
            for (int c = 0; c < 6; c++) cv[c] = w0[c] + 2.0f * w1[c] + w2[c];

            #pragma unroll
            for (int c = 1; c <= 4; c++) {
                const float sgx = cv[c + 1] - cv[c - 1];
                const float sgy = (w2[c - 1] + 2.0f * w2[c] + w2[c + 1])
                                - (w0[c - 1] + 2.0f * w0[c] + w0[c + 1]);
                acc += sqrt_approx(fmaf(sgx, sgx, fmaf(sgy, sgy, 1e-6f)));
            }

            if (((r - 2) & 3) == 3) {        // r = 5, 9, ..., 33 -> 8 output rows
                const float down = acc * (1.0f / 16.0f);
                const float e = __expf(-5.0f * (down - 0.2f));
                const float sg = __fdividef(1.0f, 1.0f + e);
                if (lane < TW) {
                    out[outbase + (size_t)((r - 5) >> 2) * OUT_W] = sg * sg;
                }
                acc = 0.0f;
            }
        }

        // Shift windows (register renames under full unroll)
        hb0 = hb1; hb1 = hb2; hb2 = hb3; hb3 = h4;
        #pragma unroll
        for (int c = 0; c < 6; c++) { w0[c] = w1[c]; w1[c] = w2[c]; }
    }
}

extern "C" void kernel_launch(void* const* d_in, const int* in_sizes, int n_in,
                              void* d_out, int out_size)
{
    const float* in = (const float*)d_in[0];
    float* out = (float*)d_out;

    // 8 col tiles (2 warps per block) x 17 row strips x 16 batch
    dim3 grid(4, 17, 16);                    // 1088 blocks of 64 threads
    EdgeGuidance_47313359733145_kernel<<<grid, 64>>>(in, out);
}